// round 15
// baseline (speedup 1.0000x reference)
#include <cuda_runtime.h>
#include <cuda_fp16.h>
#include <cstdint>

#define B_  4
#define C_  128
#define N_  4096
#define CO_ 128
#define NKT 128            // 32-key tiles

// -------- scratch device globals --------
__device__ float    g_Qt[B_ * C_ * N_];
__device__ float    g_Kt[B_ * C_ * N_];
__device__ float    g_Vt[B_ * C_ * N_];
__device__ uint32_t g_Qh[B_ * 4096 * 64];     // [b][i][crow] fp16x2 hi (Q pre-scaled by log2e)
__device__ uint32_t g_Ql[B_ * 4096 * 64];     // lo
__device__ uint32_t g_Kf[B_ * NKT * 2048];    // frag-packed fp16 K tiles
__device__ uint32_t g_Vf[B_ * NKT * 2048];    // frag-packed fp16 V tiles
__device__ float    g_SA[B_ * C_ * N_];       // attention output (post gamma+residual)

// -------- helpers --------
__device__ __forceinline__ float ex2f(float x) {
    float r;
    asm("ex2.approx.f32 %0, %1;" : "=f"(r) : "f"(x));
    return r;
}
__device__ __forceinline__ uint32_t f16x2(float lo, float hi) {
    uint32_t r;
    asm("cvt.rn.f16x2.f32 %0, %1, %2;" : "=r"(r) : "f"(hi), "f"(lo));
    return r;
}
__device__ __forceinline__ void fp16_split(float x, float& h, float& l) {
    __half hh = __float2half_rn(x);
    h = __half2float(hh);
    l = x - h;
}
__device__ __forceinline__ void mma_fp16(float* c, const uint32_t* a,
                                         uint32_t b0, uint32_t b1) {
    asm volatile(
        "mma.sync.aligned.m16n8k16.row.col.f32.f16.f16.f32 "
        "{%0,%1,%2,%3}, {%4,%5,%6,%7}, {%8,%9}, {%0,%1,%2,%3};"
        : "+f"(c[0]), "+f"(c[1]), "+f"(c[2]), "+f"(c[3])
        : "r"(a[0]), "r"(a[1]), "r"(a[2]), "r"(a[3]), "r"(b0), "r"(b1));
}
__device__ __forceinline__ void cp_async16(uint32_t dst, const void* src) {
    asm volatile("cp.async.cg.shared.global [%0], [%1], 16;" :: "r"(dst), "l"(src));
}
__device__ __forceinline__ void cp_commit() { asm volatile("cp.async.commit_group;"); }
__device__ __forceinline__ void cp_wait1()  { asm volatile("cp.async.wait_group 1;"); }

// ---------------------------------------------------------------------------
// QKV projection, one launch: z = 0(Q), 1(K), 2(V). fp32 GEMM, fp32 dst.
// ---------------------------------------------------------------------------
__global__ __launch_bounds__(256) void proj3_kernel(
    const float* __restrict__ src,
    const float* __restrict__ Wq, const float* __restrict__ bq,
    const float* __restrict__ Wk, const float* __restrict__ bk,
    const float* __restrict__ Wv, const float* __restrict__ bv)
{
    __shared__ float Wt[32][132];
    __shared__ float xs[32][64];

    const int t = threadIdx.x, nblk = blockIdx.x, b = blockIdx.y, z = blockIdx.z;
    const int n0 = 8 * (t & 7), o0 = 4 * (t >> 3);

    const float* W    = (z == 0) ? Wq : (z == 1) ? Wk : Wv;
    const float* bias = (z == 0) ? bq : (z == 1) ? bk : bv;
    float* dst        = (z == 0) ? g_Qt : (z == 1) ? g_Kt : g_Vt;

    float acc[4][8];
#pragma unroll
    for (int i = 0; i < 4; i++)
#pragma unroll
        for (int j = 0; j < 8; j++) acc[i][j] = 0.f;

    const float* srcB = src + (size_t)b * C_ * N_ + (size_t)nblk * 64;

    for (int k0 = 0; k0 < C_; k0 += 32) {
        for (int v = t; v < 1024; v += 256) {
            int o = v >> 3, q = v & 7;
            float4 w = *(const float4*)(W + (size_t)o * C_ + k0 + 4 * q);
            Wt[4 * q + 0][o] = w.x;
            Wt[4 * q + 1][o] = w.y;
            Wt[4 * q + 2][o] = w.z;
            Wt[4 * q + 3][o] = w.w;
        }
        for (int v = t; v < 512; v += 256) {
            int k = v >> 4, q = (v & 15) * 4;
            *(float4*)&xs[k][q] = *(const float4*)(srcB + (size_t)(k0 + k) * N_ + q);
        }
        __syncthreads();
#pragma unroll
        for (int k = 0; k < 32; k++) {
            float4 w  = *(float4*)&Wt[k][o0];
            float4 xa = *(float4*)&xs[k][n0];
            float4 xb = *(float4*)&xs[k][n0 + 4];
            float wv[4] = {w.x, w.y, w.z, w.w};
            float xv[8] = {xa.x, xa.y, xa.z, xa.w, xb.x, xb.y, xb.z, xb.w};
#pragma unroll
            for (int i = 0; i < 4; i++)
#pragma unroll
                for (int j = 0; j < 8; j++)
                    acc[i][j] = fmaf(wv[i], xv[j], acc[i][j]);
        }
        __syncthreads();
    }

#pragma unroll
    for (int i = 0; i < 4; i++) {
        float bv2 = bias[o0 + i];
        float* drow = dst + ((size_t)b * 128 + (o0 + i)) * N_ + (size_t)nblk * 64 + n0;
        *(float4*)(drow)     = make_float4(acc[i][0] + bv2, acc[i][1] + bv2, acc[i][2] + bv2, acc[i][3] + bv2);
        *(float4*)(drow + 4) = make_float4(acc[i][4] + bv2, acc[i][5] + bv2, acc[i][6] + bv2, acc[i][7] + bv2);
    }
}

// ---------------------------------------------------------------------------
// out-proj (fp32): dst = Wo @ g_SA + bo
// ---------------------------------------------------------------------------
__global__ __launch_bounds__(256) void proj_kernel(
    const float* __restrict__ src, const float* __restrict__ W,
    const float* __restrict__ bias, float* __restrict__ dst)
{
    __shared__ float Wt[32][132];
    __shared__ float xs[32][64];

    const int t = threadIdx.x, nblk = blockIdx.x, b = blockIdx.y;
    const int n0 = 8 * (t & 7), o0 = 4 * (t >> 3);

    float acc[4][8];
#pragma unroll
    for (int i = 0; i < 4; i++)
#pragma unroll
        for (int j = 0; j < 8; j++) acc[i][j] = 0.f;

    const float* srcB = src + (size_t)b * C_ * N_ + (size_t)nblk * 64;

    for (int k0 = 0; k0 < C_; k0 += 32) {
        for (int v = t; v < 1024; v += 256) {
            int o = v >> 3, q = v & 7;
            float4 w = *(const float4*)(W + (size_t)o * C_ + k0 + 4 * q);
            Wt[4 * q + 0][o] = w.x;
            Wt[4 * q + 1][o] = w.y;
            Wt[4 * q + 2][o] = w.z;
            Wt[4 * q + 3][o] = w.w;
        }
        for (int v = t; v < 512; v += 256) {
            int k = v >> 4, q = (v & 15) * 4;
            *(float4*)&xs[k][q] = *(const float4*)(srcB + (size_t)(k0 + k) * N_ + q);
        }
        __syncthreads();
#pragma unroll
        for (int k = 0; k < 32; k++) {
            float4 w  = *(float4*)&Wt[k][o0];
            float4 xa = *(float4*)&xs[k][n0];
            float4 xb = *(float4*)&xs[k][n0 + 4];
            float wv[4] = {w.x, w.y, w.z, w.w};
            float xv[8] = {xa.x, xa.y, xa.z, xa.w, xb.x, xb.y, xb.z, xb.w};
#pragma unroll
            for (int i = 0; i < 4; i++)
#pragma unroll
                for (int j = 0; j < 8; j++)
                    acc[i][j] = fmaf(wv[i], xv[j], acc[i][j]);
        }
        __syncthreads();
    }

#pragma unroll
    for (int i = 0; i < 4; i++) {
        float bv = bias[o0 + i];
        float* drow = dst + ((size_t)b * 128 + (o0 + i)) * N_ + (size_t)nblk * 64 + n0;
        *(float4*)(drow)     = make_float4(acc[i][0] + bv, acc[i][1] + bv, acc[i][2] + bv, acc[i][3] + bv);
        *(float4*)(drow + 4) = make_float4(acc[i][4] + bv, acc[i][5] + bv, acc[i][6] + bv, acc[i][7] + bv);
    }
}

// ---------------------------------------------------------------------------
// Merged pack kernel: z = 0(Q, pre-scaled by log2e), 1(K), 2(V).
// ---------------------------------------------------------------------------
__global__ __launch_bounds__(256) void pack_qkv_kernel()
{
    __shared__ float st[128 * 68];
    const int t = threadIdx.x, nblk = blockIdx.x, b = blockIdx.y, which = blockIdx.z;

    const float* src = (which == 0) ? g_Qt : (which == 1) ? g_Kt : g_Vt;
    const float* srcB = src + (size_t)b * C_ * N_ + (size_t)nblk * 64;
    for (int v = t; v < 2048; v += 256) {
        int c = v >> 4, q = (v & 15) * 4;
        *(float4*)&st[c * 68 + q] = *(const float4*)(srcB + (size_t)c * N_ + q);
    }
    __syncthreads();

    if (which == 0) {
        const float LOG2E = 1.4426950408889634f;
        for (int idx = t; idx < 4096; idx += 256) {
            int crow = idx & 63, nl = idx >> 6;
            int n = nblk * 64 + nl;
            float ha, la, hb, lb;
            fp16_split(st[(2 * crow) * 68 + nl] * LOG2E, ha, la);
            fp16_split(st[(2 * crow + 1) * 68 + nl] * LOG2E, hb, lb);
            size_t qb = ((size_t)b * 4096 + n) * 64 + crow;
            g_Qh[qb] = f16x2(ha, hb);
            g_Ql[qb] = f16x2(la, lb);
        }
    } else if (which == 1) {
#pragma unroll
        for (int it = 0; it < 2; it++) {
            size_t base = ((size_t)b * NKT + (size_t)nblk * 2 + it) * 2048;
            for (int u = t; u < 512; u += 256) {
                int lane = u & 31, jfp = (u >> 5) & 1, kc = u >> 6;
                int tid = lane & 3, g2 = lane >> 2;
                int nl_e = it * 32 + 16 * jfp + g2;
                int nl_o = nl_e + 8;
                int c0 = 16 * kc + 2 * tid;
                uint4 w4;
                w4.x = f16x2(st[c0 * 68 + nl_e],       st[(c0 + 1) * 68 + nl_e]);
                w4.y = f16x2(st[(c0 + 8) * 68 + nl_e], st[(c0 + 9) * 68 + nl_e]);
                w4.z = f16x2(st[c0 * 68 + nl_o],       st[(c0 + 1) * 68 + nl_o]);
                w4.w = f16x2(st[(c0 + 8) * 68 + nl_o], st[(c0 + 9) * 68 + nl_o]);
                *(uint4*)&g_Kf[base + (size_t)u * 4] = w4;
            }
        }
    } else {
#pragma unroll
        for (int it = 0; it < 2; it++) {
            size_t base = ((size_t)b * NKT + (size_t)nblk * 2 + it) * 2048;
            for (int u = t; u < 512; u += 256) {
                int lane = u & 31, nfp = (u >> 5) & 7, kc = u >> 8;
                int tid = lane & 3, g2 = lane >> 2;
                int c_e = 16 * nfp + g2;
                int c_o = c_e + 8;
                int j0 = it * 32 + 16 * kc + 2 * tid;
                uint4 w4;
                w4.x = f16x2(st[c_e * 68 + j0],     st[c_e * 68 + j0 + 1]);
                w4.y = f16x2(st[c_e * 68 + j0 + 8], st[c_e * 68 + j0 + 9]);
                w4.z = f16x2(st[c_o * 68 + j0],     st[c_o * 68 + j0 + 1]);
                w4.w = f16x2(st[c_o * 68 + j0 + 8], st[c_o * 68 + j0 + 9]);
                *(uint4*)&g_Vf[base + (size_t)u * 4] = w4;
            }
        }
    }
}

// ---------------------------------------------------------------------------
// attn (r9 structure): 256 thr / 8 warps, 128-query tile, all 128 key tiles.
// Q fragments in REGISTERS; log2-domain ex2 softmax; skip-rescale vote;
// direct gamma+residual epilogue into g_SA.
// ---------------------------------------------------------------------------
#define OFF_K 0                     // 2 stages x 2048
#define OFF_V 4096                  // 2 stages x 2048
#define SM_UINTS (128 * 132)        // O staging [128][132] covers the 8192 pipeline
#define ATTN_SMEM_BYTES (SM_UINTS * 4)

__global__ __launch_bounds__(256) void attn_kernel(
    const float* __restrict__ x, const float* __restrict__ gamma)
{
    extern __shared__ uint32_t smu[];

    const int t = threadIdx.x;
    const int w = t >> 5, lane = t & 31;
    const int g2 = lane >> 2, tid = lane & 3;
    const int qblk = blockIdx.x, b = blockIdx.y;
    const int N0 = qblk * 128;
    const int I0 = N0 + 16 * w;

    const uint32_t sbase = (uint32_t)__cvta_generic_to_shared(smu);

    // ---- Q A-fragments (fp16 hi/lo) into registers ----
    uint32_t qh[8][4], ql[8][4];
    {
        const uint32_t* Qhg = g_Qh + ((size_t)b * 4096 + I0) * 64;
        const uint32_t* Qlg = g_Ql + ((size_t)b * 4096 + I0) * 64;
        const int r0c = g2 * 64, r8c = (g2 + 8) * 64;
#pragma unroll
        for (int kc = 0; kc < 8; kc++) {
            int cl = 8 * kc + tid;
            qh[kc][0] = Qhg[r0c + cl];     qh[kc][1] = Qhg[r8c + cl];
            qh[kc][2] = Qhg[r0c + cl + 4]; qh[kc][3] = Qhg[r8c + cl + 4];
            ql[kc][0] = Qlg[r0c + cl];     ql[kc][1] = Qlg[r8c + cl];
            ql[kc][2] = Qlg[r0c + cl + 4]; ql[kc][3] = Qlg[r8c + cl + 4];
        }
    }

    const uint32_t* Kg = g_Kf + (size_t)b * NKT * 2048;
    const uint32_t* Vg = g_Vf + (size_t)b * NKT * 2048;

    auto issue = [&](int s, int kt) {
#pragma unroll
        for (int r = 0; r < 2; r++) {
            int i4 = t + 256 * r;       // uint4 index 0..511
            cp_async16(sbase + (OFF_K + s * 2048) * 4 + i4 * 16,
                       Kg + (size_t)kt * 2048 + i4 * 4);
            cp_async16(sbase + (OFF_V + s * 2048) * 4 + i4 * 16,
                       Vg + (size_t)kt * 2048 + i4 * 4);
        }
    };

    issue(0, 0); cp_commit();
    issue(1, 1); cp_commit();

    float oacc[16][4];
#pragma unroll
    for (int nf = 0; nf < 16; nf++)
#pragma unroll
        for (int r = 0; r < 4; r++) oacc[nf][r] = 0.f;
    float m0 = -1e30f, m1 = -1e30f, l0 = 0.f, l1 = 0.f;

    for (int kt = 0; kt < NKT; kt++) {
        cp_wait1();
        __syncthreads();
        const int s = kt & 1;
        const uint32_t* Kf = smu + OFF_K + s * 2048;
        const uint32_t* Vf = smu + OFF_V + s * 2048;

        // ---- S = Q^T K (2-term fp16 split, log2 domain) ----
        float sacc[4][4];
#pragma unroll
        for (int jf = 0; jf < 4; jf++)
#pragma unroll
            for (int r = 0; r < 4; r++) sacc[jf][r] = 0.f;

#pragma unroll
        for (int kc = 0; kc < 8; kc++) {
#pragma unroll
            for (int jfp = 0; jfp < 2; jfp++) {
                uint4 kb = *(const uint4*)&Kf[((kc * 2 + jfp) * 32 + lane) * 4];
                mma_fp16(sacc[2 * jfp],     qh[kc], kb.x, kb.y);
                mma_fp16(sacc[2 * jfp],     ql[kc], kb.x, kb.y);
                mma_fp16(sacc[2 * jfp + 1], qh[kc], kb.z, kb.w);
                mma_fp16(sacc[2 * jfp + 1], ql[kc], kb.z, kb.w);
            }
        }

        // ---- online softmax (ex2, log2 domain, skip-rescale vote) ----
        float mx0 = fmaxf(fmaxf(sacc[0][0], sacc[0][1]), fmaxf(sacc[1][0], sacc[1][1]));
        mx0 = fmaxf(mx0, fmaxf(fmaxf(sacc[2][0], sacc[2][1]), fmaxf(sacc[3][0], sacc[3][1])));
        float mx1 = fmaxf(fmaxf(sacc[0][2], sacc[0][3]), fmaxf(sacc[1][2], sacc[1][3]));
        mx1 = fmaxf(mx1, fmaxf(fmaxf(sacc[2][2], sacc[2][3]), fmaxf(sacc[3][2], sacc[3][3])));
        mx0 = fmaxf(mx0, __shfl_xor_sync(0xffffffffu, mx0, 1));
        mx0 = fmaxf(mx0, __shfl_xor_sync(0xffffffffu, mx0, 2));
        mx1 = fmaxf(mx1, __shfl_xor_sync(0xffffffffu, mx1, 1));
        mx1 = fmaxf(mx1, __shfl_xor_sync(0xffffffffu, mx1, 2));

        const bool upd = (mx0 > m0) || (mx1 > m1);
        if (__any_sync(0xffffffffu, upd)) {
            float mn0 = fmaxf(m0, mx0), mn1 = fmaxf(m1, mx1);
            float sc0 = ex2f(m0 - mn0), sc1 = ex2f(m1 - mn1);
            m0 = mn0; m1 = mn1;
            l0 *= sc0; l1 *= sc1;
#pragma unroll
            for (int nf = 0; nf < 16; nf++) {
                oacc[nf][0] *= sc0; oacc[nf][1] *= sc0;
                oacc[nf][2] *= sc1; oacc[nf][3] *= sc1;
            }
        }

        float rs0 = 0.f, rs1 = 0.f;
#pragma unroll
        for (int jf = 0; jf < 4; jf++) {
            sacc[jf][0] = ex2f(sacc[jf][0] - m0);
            sacc[jf][1] = ex2f(sacc[jf][1] - m0);
            sacc[jf][2] = ex2f(sacc[jf][2] - m1);
            sacc[jf][3] = ex2f(sacc[jf][3] - m1);
            rs0 += sacc[jf][0] + sacc[jf][1];
            rs1 += sacc[jf][2] + sacc[jf][3];
        }
        l0 += rs0;                 // lane-partial; reduced after the loop
        l1 += rs1;

        // ---- O += P V (P from sacc registers) ----
#pragma unroll
        for (int kc = 0; kc < 2; kc++) {
            uint32_t pa[4];
            pa[0] = f16x2(sacc[2 * kc][0],     sacc[2 * kc][1]);
            pa[1] = f16x2(sacc[2 * kc][2],     sacc[2 * kc][3]);
            pa[2] = f16x2(sacc[2 * kc + 1][0], sacc[2 * kc + 1][1]);
            pa[3] = f16x2(sacc[2 * kc + 1][2], sacc[2 * kc + 1][3]);
#pragma unroll
            for (int nfp = 0; nfp < 8; nfp++) {
                uint4 vb = *(const uint4*)&Vf[((kc * 8 + nfp) * 32 + lane) * 4];
                mma_fp16(oacc[2 * nfp],     pa, vb.x, vb.y);
                mma_fp16(oacc[2 * nfp + 1], pa, vb.z, vb.w);
            }
        }

        __syncthreads();
        if (kt + 2 < NKT) issue(s, kt + 2);
        cp_commit();
    }

    // ---- reduce l across the 4 tid lanes ----
    l0 += __shfl_xor_sync(0xffffffffu, l0, 1);
    l0 += __shfl_xor_sync(0xffffffffu, l0, 2);
    l1 += __shfl_xor_sync(0xffffffffu, l1, 1);
    l1 += __shfl_xor_sync(0xffffffffu, l1, 2);

    __syncthreads();   // all warps done with K/V smem before reuse as O staging

    // ---- normalize, stage O [128c][132], gamma+residual, write g_SA ----
    const int r0 = 16 * w + g2;
    float* OSf = (float*)smu;
    {
        float inv0 = 1.f / l0, inv1 = 1.f / l1;
#pragma unroll
        for (int nf = 0; nf < 16; nf++) {
            int c = 8 * nf + 2 * tid;
            OSf[c * 132 + r0]           = oacc[nf][0] * inv0;
            OSf[(c + 1) * 132 + r0]     = oacc[nf][1] * inv0;
            OSf[c * 132 + r0 + 8]       = oacc[nf][2] * inv1;
            OSf[(c + 1) * 132 + r0 + 8] = oacc[nf][3] * inv1;
        }
    }
    __syncthreads();

    const float gm = gamma[0];
    const float* xB  = x    + (size_t)b * C_ * N_ + N0;
    float*       saB = g_SA + (size_t)b * C_ * N_ + N0;
    for (int v = t; v < 4096; v += 256) {
        int c = v >> 5, q = (v & 31) * 4;
        float4 o  = *(float4*)&OSf[c * 132 + q];
        float4 xv = *(const float4*)(xB + (size_t)c * N_ + q);
        float4 rr = make_float4(gm * o.x + xv.x, gm * o.y + xv.y,
                                gm * o.z + xv.z, gm * o.w + xv.w);
        *(float4*)(saB + (size_t)c * N_ + q) = rr;
    }
}

// ---------------------------------------------------------------------------
extern "C" void kernel_launch(void* const* d_in, const int* in_sizes, int n_in,
                              void* d_out, int out_size)
{
    const float* x     = (const float*)d_in[0];
    const float* Wq    = (const float*)d_in[1];
    const float* bq    = (const float*)d_in[2];
    const float* Wk    = (const float*)d_in[3];
    const float* bk    = (const float*)d_in[4];
    const float* Wv    = (const float*)d_in[5];
    const float* bv    = (const float*)d_in[6];
    const float* gamma = (const float*)d_in[7];
    const float* Wo    = (const float*)d_in[8];
    const float* bo    = (const float*)d_in[9];
    float* out = (float*)d_out;

    float* SAp;
    cudaGetSymbolAddress((void**)&SAp, g_SA);

    cudaFuncSetAttribute(attn_kernel,
                         cudaFuncAttributeMaxDynamicSharedMemorySize, ATTN_SMEM_BYTES);

    dim3 p3grid(N_ / 64, B_, 3);
    proj3_kernel<<<p3grid, 256>>>(x, Wq, bq, Wk, bk, Wv, bv);
    pack_qkv_kernel<<<p3grid, 256>>>();

    dim3 agrid(N_ / 128, B_);
    attn_kernel<<<agrid, 256, ATTN_SMEM_BYTES>>>(x, gamma);

    dim3 ogrid(N_ / 64, B_);
    proj_kernel<<<ogrid, 256>>>(SAp, Wo, bo, out);
}

// round 16
// speedup vs baseline: 1.1197x; 1.1197x over previous
#include <cuda_runtime.h>
#include <cuda_fp16.h>
#include <cstdint>

#define B_  4
#define C_  128
#define N_  4096
#define NKT 128            // 32-key tiles total
#define HKT 64             // tiles per split-K half

// -------- scratch device globals --------
__device__ float    g_Qt[B_ * C_ * N_];
__device__ float    g_Kt[B_ * C_ * N_];
__device__ float    g_Vt[B_ * C_ * N_];
__device__ uint32_t g_Qh[B_ * 4096 * 64];     // [b][i][crow] fp16x2 hi (Q pre-scaled by log2e)
__device__ uint32_t g_Ql[B_ * 4096 * 64];     // lo
__device__ uint32_t g_Kf[B_ * NKT * 2048];    // frag-packed fp16 K tiles
__device__ uint32_t g_Vf[B_ * NKT * 2048];    // frag-packed fp16 V tiles
__device__ float    g_Op[2 * B_ * C_ * N_];   // unnormalized partial O per half
__device__ float    g_m [2 * B_ * N_];        // log2-domain running max
__device__ float    g_l [2 * B_ * N_];

// -------- helpers --------
__device__ __forceinline__ float ex2f(float x) {
    float r;
    asm("ex2.approx.f32 %0, %1;" : "=f"(r) : "f"(x));
    return r;
}
__device__ __forceinline__ uint32_t f16x2(float lo, float hi) {
    uint32_t r;
    asm("cvt.rn.f16x2.f32 %0, %1, %2;" : "=r"(r) : "f"(hi), "f"(lo));
    return r;
}
__device__ __forceinline__ void fp16_split(float x, float& h, float& l) {
    __half hh = __float2half_rn(x);
    h = __half2float(hh);
    l = x - h;
}
__device__ __forceinline__ void mma_fp16(float* c, const uint32_t* a,
                                         uint32_t b0, uint32_t b1) {
    asm volatile(
        "mma.sync.aligned.m16n8k16.row.col.f32.f16.f16.f32 "
        "{%0,%1,%2,%3}, {%4,%5,%6,%7}, {%8,%9}, {%0,%1,%2,%3};"
        : "+f"(c[0]), "+f"(c[1]), "+f"(c[2]), "+f"(c[3])
        : "r"(a[0]), "r"(a[1]), "r"(a[2]), "r"(a[3]), "r"(b0), "r"(b1));
}
__device__ __forceinline__ void cp_async16(uint32_t dst, const void* src) {
    asm volatile("cp.async.cg.shared.global [%0], [%1], 16;" :: "r"(dst), "l"(src));
}
__device__ __forceinline__ void cp_commit() { asm volatile("cp.async.commit_group;"); }
__device__ __forceinline__ void cp_wait1()  { asm volatile("cp.async.wait_group 1;"); }

// ---------------------------------------------------------------------------
// QKV projection, one launch: z = 0(Q), 1(K), 2(V). fp32 GEMM, fp32 dst.
// ---------------------------------------------------------------------------
__global__ __launch_bounds__(256) void proj3_kernel(
    const float* __restrict__ src,
    const float* __restrict__ Wq, const float* __restrict__ bq,
    const float* __restrict__ Wk, const float* __restrict__ bk,
    const float* __restrict__ Wv, const float* __restrict__ bv)
{
    __shared__ float Wt[32][132];
    __shared__ float xs[32][64];

    const int t = threadIdx.x, nblk = blockIdx.x, b = blockIdx.y, z = blockIdx.z;
    const int n0 = 8 * (t & 7), o0 = 4 * (t >> 3);

    const float* W    = (z == 0) ? Wq : (z == 1) ? Wk : Wv;
    const float* bias = (z == 0) ? bq : (z == 1) ? bk : bv;
    float* dst        = (z == 0) ? g_Qt : (z == 1) ? g_Kt : g_Vt;

    float acc[4][8];
#pragma unroll
    for (int i = 0; i < 4; i++)
#pragma unroll
        for (int j = 0; j < 8; j++) acc[i][j] = 0.f;

    const float* srcB = src + (size_t)b * C_ * N_ + (size_t)nblk * 64;

    for (int k0 = 0; k0 < C_; k0 += 32) {
        for (int v = t; v < 1024; v += 256) {
            int o = v >> 3, q = v & 7;
            float4 w = *(const float4*)(W + (size_t)o * C_ + k0 + 4 * q);
            Wt[4 * q + 0][o] = w.x;
            Wt[4 * q + 1][o] = w.y;
            Wt[4 * q + 2][o] = w.z;
            Wt[4 * q + 3][o] = w.w;
        }
        for (int v = t; v < 512; v += 256) {
            int k = v >> 4, q = (v & 15) * 4;
            *(float4*)&xs[k][q] = *(const float4*)(srcB + (size_t)(k0 + k) * N_ + q);
        }
        __syncthreads();
#pragma unroll
        for (int k = 0; k < 32; k++) {
            float4 w  = *(float4*)&Wt[k][o0];
            float4 xa = *(float4*)&xs[k][n0];
            float4 xb = *(float4*)&xs[k][n0 + 4];
            float wv[4] = {w.x, w.y, w.z, w.w};
            float xv[8] = {xa.x, xa.y, xa.z, xa.w, xb.x, xb.y, xb.z, xb.w};
#pragma unroll
            for (int i = 0; i < 4; i++)
#pragma unroll
                for (int j = 0; j < 8; j++)
                    acc[i][j] = fmaf(wv[i], xv[j], acc[i][j]);
        }
        __syncthreads();
    }

#pragma unroll
    for (int i = 0; i < 4; i++) {
        float bv2 = bias[o0 + i];
        float* drow = dst + ((size_t)b * 128 + (o0 + i)) * N_ + (size_t)nblk * 64 + n0;
        *(float4*)(drow)     = make_float4(acc[i][0] + bv2, acc[i][1] + bv2, acc[i][2] + bv2, acc[i][3] + bv2);
        *(float4*)(drow + 4) = make_float4(acc[i][4] + bv2, acc[i][5] + bv2, acc[i][6] + bv2, acc[i][7] + bv2);
    }
}

// ---------------------------------------------------------------------------
// Merged pack kernel: z = 0(Q, pre-scaled by log2e), 1(K), 2(V).
// ---------------------------------------------------------------------------
__global__ __launch_bounds__(256) void pack_qkv_kernel()
{
    __shared__ float st[128 * 68];
    const int t = threadIdx.x, nblk = blockIdx.x, b = blockIdx.y, which = blockIdx.z;

    const float* src = (which == 0) ? g_Qt : (which == 1) ? g_Kt : g_Vt;
    const float* srcB = src + (size_t)b * C_ * N_ + (size_t)nblk * 64;
    for (int v = t; v < 2048; v += 256) {
        int c = v >> 4, q = (v & 15) * 4;
        *(float4*)&st[c * 68 + q] = *(const float4*)(srcB + (size_t)c * N_ + q);
    }
    __syncthreads();

    if (which == 0) {
        const float LOG2E = 1.4426950408889634f;
        for (int idx = t; idx < 4096; idx += 256) {
            int crow = idx & 63, nl = idx >> 6;
            int n = nblk * 64 + nl;
            float ha, la, hb, lb;
            fp16_split(st[(2 * crow) * 68 + nl] * LOG2E, ha, la);
            fp16_split(st[(2 * crow + 1) * 68 + nl] * LOG2E, hb, lb);
            size_t qb = ((size_t)b * 4096 + n) * 64 + crow;
            g_Qh[qb] = f16x2(ha, hb);
            g_Ql[qb] = f16x2(la, lb);
        }
    } else if (which == 1) {
#pragma unroll
        for (int it = 0; it < 2; it++) {
            size_t base = ((size_t)b * NKT + (size_t)nblk * 2 + it) * 2048;
            for (int u = t; u < 512; u += 256) {
                int lane = u & 31, jfp = (u >> 5) & 1, kc = u >> 6;
                int tid = lane & 3, g2 = lane >> 2;
                int nl_e = it * 32 + 16 * jfp + g2;
                int nl_o = nl_e + 8;
                int c0 = 16 * kc + 2 * tid;
                uint4 w4;
                w4.x = f16x2(st[c0 * 68 + nl_e],       st[(c0 + 1) * 68 + nl_e]);
                w4.y = f16x2(st[(c0 + 8) * 68 + nl_e], st[(c0 + 9) * 68 + nl_e]);
                w4.z = f16x2(st[c0 * 68 + nl_o],       st[(c0 + 1) * 68 + nl_o]);
                w4.w = f16x2(st[(c0 + 8) * 68 + nl_o], st[(c0 + 9) * 68 + nl_o]);
                *(uint4*)&g_Kf[base + (size_t)u * 4] = w4;
            }
        }
    } else {
#pragma unroll
        for (int it = 0; it < 2; it++) {
            size_t base = ((size_t)b * NKT + (size_t)nblk * 2 + it) * 2048;
            for (int u = t; u < 512; u += 256) {
                int lane = u & 31, nfp = (u >> 5) & 7, kc = u >> 8;
                int tid = lane & 3, g2 = lane >> 2;
                int c_e = 16 * nfp + g2;
                int c_o = c_e + 8;
                int j0 = it * 32 + 16 * kc + 2 * tid;
                uint4 w4;
                w4.x = f16x2(st[c_e * 68 + j0],     st[c_e * 68 + j0 + 1]);
                w4.y = f16x2(st[c_e * 68 + j0 + 8], st[c_e * 68 + j0 + 9]);
                w4.z = f16x2(st[c_o * 68 + j0],     st[c_o * 68 + j0 + 1]);
                w4.w = f16x2(st[c_o * 68 + j0 + 8], st[c_o * 68 + j0 + 9]);
                *(uint4*)&g_Vf[base + (size_t)u * 4] = w4;
            }
        }
    }
}

// ---------------------------------------------------------------------------
// attn (split-K): grid (32, B, 2). 256 thr, 128-query tile, 64 key tiles.
// 2-stage cp.async double buffer. log2-domain ex2 softmax, skip-rescale vote.
// Q frags in smem; 2 CTAs/SM.
// ---------------------------------------------------------------------------
#define OFF_K 0                      // 2 stages x 2048
#define OFF_V 4096                   // 2 stages x 2048
#define OFF_Q 8192                   // Q frags: 16384 uints
#define SM_UINTS (8192 + 16384)      // 98304 B
#define ATTN_SMEM_BYTES (SM_UINTS * 4)

__global__ __launch_bounds__(256, 2) void attn_kernel()
{
    extern __shared__ uint32_t smu[];

    const int t = threadIdx.x;
    const int w = t >> 5, lane = t & 31;
    const int g2 = lane >> 2, tid = lane & 3;
    const int qblk = blockIdx.x, b = blockIdx.y, half = blockIdx.z;
    const int N0 = qblk * 128;
    const int I0 = N0 + 16 * w;

    const uint32_t sbase = (uint32_t)__cvta_generic_to_shared(smu);

    // ---- Q fragments -> smem ----
    {
        const uint32_t* Qhg = g_Qh + ((size_t)b * 4096 + I0) * 64;
        const uint32_t* Qlg = g_Ql + ((size_t)b * 4096 + I0) * 64;
        const int r0c = g2 * 64, r8c = (g2 + 8) * 64;
#pragma unroll
        for (int kc = 0; kc < 8; kc++) {
            int cl = 8 * kc + tid;
            uint4 h = make_uint4(Qhg[r0c + cl], Qhg[r8c + cl],
                                 Qhg[r0c + cl + 4], Qhg[r8c + cl + 4]);
            uint4 l = make_uint4(Qlg[r0c + cl], Qlg[r8c + cl],
                                 Qlg[r0c + cl + 4], Qlg[r8c + cl + 4]);
            *(uint4*)&smu[OFF_Q + ((w * 16 + 2 * kc) * 32 + lane) * 4]     = h;
            *(uint4*)&smu[OFF_Q + ((w * 16 + 2 * kc + 1) * 32 + lane) * 4] = l;
        }
    }

    const uint32_t* Kg = g_Kf + ((size_t)b * NKT + (size_t)half * HKT) * 2048;
    const uint32_t* Vg = g_Vf + ((size_t)b * NKT + (size_t)half * HKT) * 2048;

    auto issue = [&](int s, int kt) {
#pragma unroll
        for (int r = 0; r < 2; r++) {
            int i4 = t + 256 * r;
            cp_async16(sbase + (OFF_K + s * 2048) * 4 + i4 * 16,
                       Kg + (size_t)kt * 2048 + i4 * 4);
            cp_async16(sbase + (OFF_V + s * 2048) * 4 + i4 * 16,
                       Vg + (size_t)kt * 2048 + i4 * 4);
        }
    };

    issue(0, 0); cp_commit();
    issue(1, 1); cp_commit();

    float oacc[16][4];
#pragma unroll
    for (int nf = 0; nf < 16; nf++)
#pragma unroll
        for (int r = 0; r < 4; r++) oacc[nf][r] = 0.f;
    float m0 = -1e30f, m1 = -1e30f, l0 = 0.f, l1 = 0.f;

    for (int kt = 0; kt < HKT; kt++) {
        cp_wait1();
        __syncthreads();
        const int s = kt & 1;
        const uint32_t* Kf = smu + OFF_K + s * 2048;
        const uint32_t* Vf = smu + OFF_V + s * 2048;

        // ---- S = Q^T K (log2 domain) ----
        float sacc[4][4];
#pragma unroll
        for (int jf = 0; jf < 4; jf++)
#pragma unroll
            for (int r = 0; r < 4; r++) sacc[jf][r] = 0.f;

#pragma unroll
        for (int kc = 0; kc < 8; kc++) {
            uint4 qh4 = *(const uint4*)&smu[OFF_Q + ((w * 16 + 2 * kc) * 32 + lane) * 4];
            uint4 ql4 = *(const uint4*)&smu[OFF_Q + ((w * 16 + 2 * kc + 1) * 32 + lane) * 4];
            uint32_t qha[4] = {qh4.x, qh4.y, qh4.z, qh4.w};
            uint32_t qla[4] = {ql4.x, ql4.y, ql4.z, ql4.w};
#pragma unroll
            for (int jfp = 0; jfp < 2; jfp++) {
                uint4 kb = *(const uint4*)&Kf[((kc * 2 + jfp) * 32 + lane) * 4];
                mma_fp16(sacc[2 * jfp],     qha, kb.x, kb.y);
                mma_fp16(sacc[2 * jfp],     qla, kb.x, kb.y);
                mma_fp16(sacc[2 * jfp + 1], qha, kb.z, kb.w);
                mma_fp16(sacc[2 * jfp + 1], qla, kb.z, kb.w);
            }
        }

        // ---- online softmax (ex2, log2 domain) ----
        float mx0 = fmaxf(fmaxf(sacc[0][0], sacc[0][1]), fmaxf(sacc[1][0], sacc[1][1]));
        mx0 = fmaxf(mx0, fmaxf(fmaxf(sacc[2][0], sacc[2][1]), fmaxf(sacc[3][0], sacc[3][1])));
        float mx1 = fmaxf(fmaxf(sacc[0][2], sacc[0][3]), fmaxf(sacc[1][2], sacc[1][3]));
        mx1 = fmaxf(mx1, fmaxf(fmaxf(sacc[2][2], sacc[2][3]), fmaxf(sacc[3][2], sacc[3][3])));
        mx0 = fmaxf(mx0, __shfl_xor_sync(0xffffffffu, mx0, 1));
        mx0 = fmaxf(mx0, __shfl_xor_sync(0xffffffffu, mx0, 2));
        mx1 = fmaxf(mx1, __shfl_xor_sync(0xffffffffu, mx1, 1));
        mx1 = fmaxf(mx1, __shfl_xor_sync(0xffffffffu, mx1, 2));

        const bool upd = (mx0 > m0) || (mx1 > m1);
        if (__any_sync(0xffffffffu, upd)) {
            float mn0 = fmaxf(m0, mx0), mn1 = fmaxf(m1, mx1);
            float sc0 = ex2f(m0 - mn0), sc1 = ex2f(m1 - mn1);
            m0 = mn0; m1 = mn1;
            l0 *= sc0; l1 *= sc1;
#pragma unroll
            for (int nf = 0; nf < 16; nf++) {
                oacc[nf][0] *= sc0; oacc[nf][1] *= sc0;
                oacc[nf][2] *= sc1; oacc[nf][3] *= sc1;
            }
        }

        float rs0 = 0.f, rs1 = 0.f;
#pragma unroll
        for (int jf = 0; jf < 4; jf++) {
            sacc[jf][0] = ex2f(sacc[jf][0] - m0);
            sacc[jf][1] = ex2f(sacc[jf][1] - m0);
            sacc[jf][2] = ex2f(sacc[jf][2] - m1);
            sacc[jf][3] = ex2f(sacc[jf][3] - m1);
            rs0 += sacc[jf][0] + sacc[jf][1];
            rs1 += sacc[jf][2] + sacc[jf][3];
        }
        l0 += rs0;                 // lane-partial; reduced at end
        l1 += rs1;

        // ---- O += P V ----
#pragma unroll
        for (int kc = 0; kc < 2; kc++) {
            uint32_t pa[4];
            pa[0] = f16x2(sacc[2 * kc][0],     sacc[2 * kc][1]);
            pa[1] = f16x2(sacc[2 * kc][2],     sacc[2 * kc][3]);
            pa[2] = f16x2(sacc[2 * kc + 1][0], sacc[2 * kc + 1][1]);
            pa[3] = f16x2(sacc[2 * kc + 1][2], sacc[2 * kc + 1][3]);
#pragma unroll
            for (int nfp = 0; nfp < 8; nfp++) {
                uint4 vb = *(const uint4*)&Vf[((kc * 8 + nfp) * 32 + lane) * 4];
                mma_fp16(oacc[2 * nfp],     pa, vb.x, vb.y);
                mma_fp16(oacc[2 * nfp + 1], pa, vb.z, vb.w);
            }
        }

        __syncthreads();
        if (kt + 2 < HKT) issue(s, kt + 2);
        cp_commit();
    }

    // ---- reduce l across the 4 tid lanes ----
    l0 += __shfl_xor_sync(0xffffffffu, l0, 1);
    l0 += __shfl_xor_sync(0xffffffffu, l0, 2);
    l1 += __shfl_xor_sync(0xffffffffu, l1, 1);
    l1 += __shfl_xor_sync(0xffffffffu, l1, 2);

    // ---- stage O (unnormalized), write partials + m,l ----
    const int r0 = 16 * w + g2;
    float* OSf = (float*)smu;           // [128][132]
#pragma unroll
    for (int nf = 0; nf < 16; nf++) {
        int c = 8 * nf + 2 * tid;
        OSf[c * 132 + r0]           = oacc[nf][0];
        OSf[(c + 1) * 132 + r0]     = oacc[nf][1];
        OSf[c * 132 + r0 + 8]       = oacc[nf][2];
        OSf[(c + 1) * 132 + r0 + 8] = oacc[nf][3];
    }
    if (tid == 0) {
        size_t lb = ((size_t)half * B_ + b) * 4096 + N0;
        g_m[lb + r0]     = m0;
        g_m[lb + r0 + 8] = m1;
        g_l[lb + r0]     = l0;
        g_l[lb + r0 + 8] = l1;
    }
    __syncthreads();

    float* Og = g_Op + ((size_t)half * B_ + b) * (size_t)C_ * N_ + N0;
    for (int v = t; v < 4096; v += 256) {
        int c = v >> 5, q = (v & 31) * 4;
        *(float4*)(Og + (size_t)c * N_ + q) = *(float4*)&OSf[c * 132 + q];
    }
}

// ---------------------------------------------------------------------------
// out-proj fused with split-K combine + gamma + residual, cp.async pipelined.
// grid (64, B), 256 thr. dynamic smem.
// smem floats: Wt 4224 | xs 2048 | raw[2][3][2048] | w1s 64 | w2s 64
// ---------------------------------------------------------------------------
#define OP_W   0
#define OP_XS  4224
#define OP_RAW 6272
#define OP_W1  18560
#define OP_W2  18624
#define OP_FLOATS 18688
#define OP_SMEM_BYTES (OP_FLOATS * 4)

__global__ __launch_bounds__(256) void outproj_kernel(
    const float* __restrict__ x, const float* __restrict__ gamma,
    const float* __restrict__ W, const float* __restrict__ bias,
    float* __restrict__ dst)
{
    extern __shared__ float osm[];
    float* Wt  = osm + OP_W;     // [32][132]
    float* xs  = osm + OP_XS;    // [32][64]
    float* w1s = osm + OP_W1;
    float* w2s = osm + OP_W2;

    const int t = threadIdx.x, nblk = blockIdx.x, b = blockIdx.y;
    const int n0 = 8 * (t & 7), o0 = 4 * (t >> 3);
    const int nbase = nblk * 64;

    const uint32_t sbase = (uint32_t)__cvta_generic_to_shared(osm);

    const float* O1 = g_Op + (size_t)b * C_ * N_ + nbase;
    const float* O2 = g_Op + (size_t)(B_ + b) * C_ * N_ + nbase;
    const float* xB = x + (size_t)b * C_ * N_ + nbase;

    // issue cp.async for chunk kc (rows kc*32 .. +31) into stage s
    auto issue = [&](int s, int kc) {
        const float* srcs[3] = {O1, O2, xB};
#pragma unroll
        for (int p = 0; p < 3; p++) {
#pragma unroll
            for (int r = 0; r < 2; r++) {
                int v = t + 256 * r;          // float4 index 0..511
                int k = v >> 4, q = (v & 15) * 4;
                cp_async16(sbase + (OP_RAW + ((s * 3 + p) * 2048) + v * 4) * 4,
                           srcs[p] + (size_t)(kc * 32 + k) * N_ + q);
            }
        }
    };

    issue(0, 0); cp_commit();
    issue(1, 1); cp_commit();

    // combine weights
    if (t < 64) {
        size_t i1 = (size_t)b * 4096 + nbase + t;
        size_t i2 = (size_t)(B_ + b) * 4096 + nbase + t;
        float m1 = g_m[i1], m2 = g_m[i2];
        float l1 = g_l[i1], l2 = g_l[i2];
        float m = fmaxf(m1, m2);
        float f1 = ex2f(m1 - m), f2 = ex2f(m2 - m);
        float inv = 1.f / (l1 * f1 + l2 * f2);
        w1s[t] = f1 * inv;
        w2s[t] = f2 * inv;
    }

    const float gm = gamma[0];

    float acc[4][8];
#pragma unroll
    for (int i = 0; i < 4; i++)
#pragma unroll
        for (int j = 0; j < 8; j++) acc[i][j] = 0.f;

#pragma unroll
    for (int kc = 0; kc < 4; kc++) {
        const int s = kc & 1;
        // load Wt chunk (L2-hot, regular loads)
        for (int v = t; v < 1024; v += 256) {
            int o = v >> 3, q = v & 7;
            float4 w = *(const float4*)(W + (size_t)o * C_ + kc * 32 + 4 * q);
            Wt[(4 * q + 0) * 132 + o] = w.x;
            Wt[(4 * q + 1) * 132 + o] = w.y;
            Wt[(4 * q + 2) * 132 + o] = w.z;
            Wt[(4 * q + 3) * 132 + o] = w.w;
        }
        cp_wait1();
        __syncthreads();

        // combine raw -> xs
        {
            const float* r1 = osm + OP_RAW + (s * 3 + 0) * 2048;
            const float* r2 = osm + OP_RAW + (s * 3 + 1) * 2048;
            const float* rx = osm + OP_RAW + (s * 3 + 2) * 2048;
            for (int v = t; v < 512; v += 256) {
                int k = v >> 4, q = (v & 15) * 4;
                float4 o1 = *(const float4*)&r1[k * 64 + q];
                float4 o2 = *(const float4*)&r2[k * 64 + q];
                float4 xv = *(const float4*)&rx[k * 64 + q];
                float4 rr;
                rr.x = gm * (o1.x * w1s[q + 0] + o2.x * w2s[q + 0]) + xv.x;
                rr.y = gm * (o1.y * w1s[q + 1] + o2.y * w2s[q + 1]) + xv.y;
                rr.z = gm * (o1.z * w1s[q + 2] + o2.z * w2s[q + 2]) + xv.z;
                rr.w = gm * (o1.w * w1s[q + 3] + o2.w * w2s[q + 3]) + xv.w;
                *(float4*)&xs[k * 64 + q] = rr;
            }
        }
        __syncthreads();

        if (kc + 2 < 4) issue(s, kc + 2);
        cp_commit();

#pragma unroll
        for (int k = 0; k < 32; k++) {
            float4 w  = *(float4*)&Wt[k * 132 + o0];
            float4 xa = *(float4*)&xs[k * 64 + n0];
            float4 xb = *(float4*)&xs[k * 64 + n0 + 4];
            float wv[4] = {w.x, w.y, w.z, w.w};
            float xv[8] = {xa.x, xa.y, xa.z, xa.w, xb.x, xb.y, xb.z, xb.w};
#pragma unroll
            for (int i = 0; i < 4; i++)
#pragma unroll
                for (int j = 0; j < 8; j++)
                    acc[i][j] = fmaf(wv[i], xv[j], acc[i][j]);
        }
        __syncthreads();
    }

#pragma unroll
    for (int i = 0; i < 4; i++) {
        float bv = bias[o0 + i];
        float* drow = dst + ((size_t)b * 128 + (o0 + i)) * N_ + (size_t)nblk * 64 + n0;
        *(float4*)(drow)     = make_float4(acc[i][0] + bv, acc[i][1] + bv, acc[i][2] + bv, acc[i][3] + bv);
        *(float4*)(drow + 4) = make_float4(acc[i][4] + bv, acc[i][5] + bv, acc[i][6] + bv, acc[i][7] + bv);
    }
}

// ---------------------------------------------------------------------------
extern "C" void kernel_launch(void* const* d_in, const int* in_sizes, int n_in,
                              void* d_out, int out_size)
{
    const float* x     = (const float*)d_in[0];
    const float* Wq    = (const float*)d_in[1];
    const float* bq    = (const float*)d_in[2];
    const float* Wk    = (const float*)d_in[3];
    const float* bk    = (const float*)d_in[4];
    const float* Wv    = (const float*)d_in[5];
    const float* bv    = (const float*)d_in[6];
    const float* gamma = (const float*)d_in[7];
    const float* Wo    = (const float*)d_in[8];
    const float* bo    = (const float*)d_in[9];
    float* out = (float*)d_out;

    cudaFuncSetAttribute(attn_kernel,
                         cudaFuncAttributeMaxDynamicSharedMemorySize, ATTN_SMEM_BYTES);
    cudaFuncSetAttribute(outproj_kernel,
                         cudaFuncAttributeMaxDynamicSharedMemorySize, OP_SMEM_BYTES);

    dim3 p3grid(N_ / 64, B_, 3);
    proj3_kernel<<<p3grid, 256>>>(x, Wq, bq, Wk, bk, Wv, bv);
    pack_qkv_kernel<<<p3grid, 256>>>();

    dim3 agrid(N_ / 128, B_, 2);
    attn_kernel<<<agrid, 256, ATTN_SMEM_BYTES>>>();

    dim3 ogrid(N_ / 64, B_);
    outproj_kernel<<<ogrid, 256, OP_SMEM_BYTES>>>(x, gamma, Wo, bo, out);
}

// round 17
// speedup vs baseline: 1.2676x; 1.1321x over previous
#include <cuda_runtime.h>
#include <cuda_fp16.h>
#include <cstdint>

#define B_  4
#define C_  128
#define N_  4096
#define NKT 128            // 32-key tiles total
#define HKT 64             // tiles per split-K half

// -------- scratch device globals --------
__device__ float    g_Qt[B_ * C_ * N_];
__device__ float    g_Kt[B_ * C_ * N_];
__device__ float    g_Vt[B_ * C_ * N_];
__device__ uint32_t g_Qh[B_ * 4096 * 64];     // [b][i][crow] fp16x2 (Q pre-scaled by log2e)
__device__ uint32_t g_Kf[B_ * NKT * 2048];    // frag-packed fp16 K tiles
__device__ uint32_t g_Vf[B_ * NKT * 2048];    // frag-packed fp16 V tiles
__device__ float    g_Op[2 * B_ * C_ * N_];   // unnormalized partial O per half
__device__ float    g_m [2 * B_ * N_];        // log2-domain running max
__device__ float    g_l [2 * B_ * N_];

// -------- helpers --------
__device__ __forceinline__ float ex2f(float x) {
    float r;
    asm("ex2.approx.f32 %0, %1;" : "=f"(r) : "f"(x));
    return r;
}
__device__ __forceinline__ uint32_t f16x2(float lo, float hi) {
    uint32_t r;
    asm("cvt.rn.f16x2.f32 %0, %1, %2;" : "=r"(r) : "f"(hi), "f"(lo));
    return r;
}
__device__ __forceinline__ void mma_fp16(float* c, const uint32_t* a,
                                         uint32_t b0, uint32_t b1) {
    asm volatile(
        "mma.sync.aligned.m16n8k16.row.col.f32.f16.f16.f32 "
        "{%0,%1,%2,%3}, {%4,%5,%6,%7}, {%8,%9}, {%0,%1,%2,%3};"
        : "+f"(c[0]), "+f"(c[1]), "+f"(c[2]), "+f"(c[3])
        : "r"(a[0]), "r"(a[1]), "r"(a[2]), "r"(a[3]), "r"(b0), "r"(b1));
}
__device__ __forceinline__ void cp_async16(uint32_t dst, const void* src) {
    asm volatile("cp.async.cg.shared.global [%0], [%1], 16;" :: "r"(dst), "l"(src));
}
__device__ __forceinline__ void cp_commit() { asm volatile("cp.async.commit_group;"); }
__device__ __forceinline__ void cp_wait1()  { asm volatile("cp.async.wait_group 1;"); }

// ---------------------------------------------------------------------------
// QKV projection, one launch: z = 0(Q), 1(K), 2(V). fp32 GEMM, fp32 dst.
// ---------------------------------------------------------------------------
__global__ __launch_bounds__(256) void proj3_kernel(
    const float* __restrict__ src,
    const float* __restrict__ Wq, const float* __restrict__ bq,
    const float* __restrict__ Wk, const float* __restrict__ bk,
    const float* __restrict__ Wv, const float* __restrict__ bv)
{
    __shared__ float Wt[32][132];
    __shared__ float xs[32][64];

    const int t = threadIdx.x, nblk = blockIdx.x, b = blockIdx.y, z = blockIdx.z;
    const int n0 = 8 * (t & 7), o0 = 4 * (t >> 3);

    const float* W    = (z == 0) ? Wq : (z == 1) ? Wk : Wv;
    const float* bias = (z == 0) ? bq : (z == 1) ? bk : bv;
    float* dst        = (z == 0) ? g_Qt : (z == 1) ? g_Kt : g_Vt;

    float acc[4][8];
#pragma unroll
    for (int i = 0; i < 4; i++)
#pragma unroll
        for (int j = 0; j < 8; j++) acc[i][j] = 0.f;

    const float* srcB = src + (size_t)b * C_ * N_ + (size_t)nblk * 64;

    for (int k0 = 0; k0 < C_; k0 += 32) {
        for (int v = t; v < 1024; v += 256) {
            int o = v >> 3, q = v & 7;
            float4 w = *(const float4*)(W + (size_t)o * C_ + k0 + 4 * q);
            Wt[4 * q + 0][o] = w.x;
            Wt[4 * q + 1][o] = w.y;
            Wt[4 * q + 2][o] = w.z;
            Wt[4 * q + 3][o] = w.w;
        }
        for (int v = t; v < 512; v += 256) {
            int k = v >> 4, q = (v & 15) * 4;
            *(float4*)&xs[k][q] = *(const float4*)(srcB + (size_t)(k0 + k) * N_ + q);
        }
        __syncthreads();
#pragma unroll
        for (int k = 0; k < 32; k++) {
            float4 w  = *(float4*)&Wt[k][o0];
            float4 xa = *(float4*)&xs[k][n0];
            float4 xb = *(float4*)&xs[k][n0 + 4];
            float wv[4] = {w.x, w.y, w.z, w.w};
            float xv[8] = {xa.x, xa.y, xa.z, xa.w, xb.x, xb.y, xb.z, xb.w};
#pragma unroll
            for (int i = 0; i < 4; i++)
#pragma unroll
                for (int j = 0; j < 8; j++)
                    acc[i][j] = fmaf(wv[i], xv[j], acc[i][j]);
        }
        __syncthreads();
    }

#pragma unroll
    for (int i = 0; i < 4; i++) {
        float bv2 = bias[o0 + i];
        float* drow = dst + ((size_t)b * 128 + (o0 + i)) * N_ + (size_t)nblk * 64 + n0;
        *(float4*)(drow)     = make_float4(acc[i][0] + bv2, acc[i][1] + bv2, acc[i][2] + bv2, acc[i][3] + bv2);
        *(float4*)(drow + 4) = make_float4(acc[i][4] + bv2, acc[i][5] + bv2, acc[i][6] + bv2, acc[i][7] + bv2);
    }
}

// ---------------------------------------------------------------------------
// Merged pack kernel: z = 0(Q, pre-scaled by log2e, single fp16), 1(K), 2(V).
// ---------------------------------------------------------------------------
__global__ __launch_bounds__(256) void pack_qkv_kernel()
{
    __shared__ float st[128 * 68];
    const int t = threadIdx.x, nblk = blockIdx.x, b = blockIdx.y, which = blockIdx.z;

    const float* src = (which == 0) ? g_Qt : (which == 1) ? g_Kt : g_Vt;
    const float* srcB = src + (size_t)b * C_ * N_ + (size_t)nblk * 64;
    for (int v = t; v < 2048; v += 256) {
        int c = v >> 4, q = (v & 15) * 4;
        *(float4*)&st[c * 68 + q] = *(const float4*)(srcB + (size_t)c * N_ + q);
    }
    __syncthreads();

    if (which == 0) {
        const float LOG2E = 1.4426950408889634f;
        for (int idx = t; idx < 4096; idx += 256) {
            int crow = idx & 63, nl = idx >> 6;
            int n = nblk * 64 + nl;
            size_t qb = ((size_t)b * 4096 + n) * 64 + crow;
            g_Qh[qb] = f16x2(st[(2 * crow) * 68 + nl] * LOG2E,
                             st[(2 * crow + 1) * 68 + nl] * LOG2E);
        }
    } else if (which == 1) {
#pragma unroll
        for (int it = 0; it < 2; it++) {
            size_t base = ((size_t)b * NKT + (size_t)nblk * 2 + it) * 2048;
            for (int u = t; u < 512; u += 256) {
                int lane = u & 31, jfp = (u >> 5) & 1, kc = u >> 6;
                int tid = lane & 3, g2 = lane >> 2;
                int nl_e = it * 32 + 16 * jfp + g2;
                int nl_o = nl_e + 8;
                int c0 = 16 * kc + 2 * tid;
                uint4 w4;
                w4.x = f16x2(st[c0 * 68 + nl_e],       st[(c0 + 1) * 68 + nl_e]);
                w4.y = f16x2(st[(c0 + 8) * 68 + nl_e], st[(c0 + 9) * 68 + nl_e]);
                w4.z = f16x2(st[c0 * 68 + nl_o],       st[(c0 + 1) * 68 + nl_o]);
                w4.w = f16x2(st[(c0 + 8) * 68 + nl_o], st[(c0 + 9) * 68 + nl_o]);
                *(uint4*)&g_Kf[base + (size_t)u * 4] = w4;
            }
        }
    } else {
#pragma unroll
        for (int it = 0; it < 2; it++) {
            size_t base = ((size_t)b * NKT + (size_t)nblk * 2 + it) * 2048;
            for (int u = t; u < 512; u += 256) {
                int lane = u & 31, nfp = (u >> 5) & 7, kc = u >> 8;
                int tid = lane & 3, g2 = lane >> 2;
                int c_e = 16 * nfp + g2;
                int c_o = c_e + 8;
                int j0 = it * 32 + 16 * kc + 2 * tid;
                uint4 w4;
                w4.x = f16x2(st[c_e * 68 + j0],     st[c_e * 68 + j0 + 1]);
                w4.y = f16x2(st[c_e * 68 + j0 + 8], st[c_e * 68 + j0 + 9]);
                w4.z = f16x2(st[c_o * 68 + j0],     st[c_o * 68 + j0 + 1]);
                w4.w = f16x2(st[c_o * 68 + j0 + 8], st[c_o * 68 + j0 + 9]);
                *(uint4*)&g_Vf[base + (size_t)u * 4] = w4;
            }
        }
    }
}

// ---------------------------------------------------------------------------
// attn (split-K): grid (32, B, 2). 256 thr, 128-query tile, 64 key tiles.
// Single-fp16 Q (32 S-mma + 32 PV-mma per warp/kt). Q frags in smem.
// ---------------------------------------------------------------------------
#define OFF_K 0                      // 2 stages x 2048
#define OFF_V 4096                   // 2 stages x 2048
#define OFF_Q 8192                   // Q frags: 8192 uints
#define SM_UINTS (128 * 132)         // O staging [128][132] = 16896 covers pipeline 16384
#define ATTN_SMEM_BYTES (SM_UINTS * 4)

__global__ __launch_bounds__(256, 2) void attn_kernel()
{
    extern __shared__ uint32_t smu[];

    const int t = threadIdx.x;
    const int w = t >> 5, lane = t & 31;
    const int g2 = lane >> 2, tid = lane & 3;
    const int qblk = blockIdx.x, b = blockIdx.y, half = blockIdx.z;
    const int N0 = qblk * 128;
    const int I0 = N0 + 16 * w;

    const uint32_t sbase = (uint32_t)__cvta_generic_to_shared(smu);

    // ---- Q fragments -> smem (single fp16) ----
    {
        const uint32_t* Qhg = g_Qh + ((size_t)b * 4096 + I0) * 64;
        const int r0c = g2 * 64, r8c = (g2 + 8) * 64;
#pragma unroll
        for (int kc = 0; kc < 8; kc++) {
            int cl = 8 * kc + tid;
            uint4 h = make_uint4(Qhg[r0c + cl], Qhg[r8c + cl],
                                 Qhg[r0c + cl + 4], Qhg[r8c + cl + 4]);
            *(uint4*)&smu[OFF_Q + ((w * 8 + kc) * 32 + lane) * 4] = h;
        }
    }

    const uint32_t* Kg = g_Kf + ((size_t)b * NKT + (size_t)half * HKT) * 2048;
    const uint32_t* Vg = g_Vf + ((size_t)b * NKT + (size_t)half * HKT) * 2048;

    auto issue = [&](int s, int kt) {
#pragma unroll
        for (int r = 0; r < 2; r++) {
            int i4 = t + 256 * r;
            cp_async16(sbase + (OFF_K + s * 2048) * 4 + i4 * 16,
                       Kg + (size_t)kt * 2048 + i4 * 4);
            cp_async16(sbase + (OFF_V + s * 2048) * 4 + i4 * 16,
                       Vg + (size_t)kt * 2048 + i4 * 4);
        }
    };

    issue(0, 0); cp_commit();
    issue(1, 1); cp_commit();

    float oacc[16][4];
#pragma unroll
    for (int nf = 0; nf < 16; nf++)
#pragma unroll
        for (int r = 0; r < 4; r++) oacc[nf][r] = 0.f;
    float m0 = -1e30f, m1 = -1e30f, l0 = 0.f, l1 = 0.f;

    for (int kt = 0; kt < HKT; kt++) {
        cp_wait1();
        __syncthreads();
        const int s = kt & 1;
        const uint32_t* Kf = smu + OFF_K + s * 2048;
        const uint32_t* Vf = smu + OFF_V + s * 2048;

        // ---- S = Q^T K (single fp16, log2 domain) : 32 mma ----
        float sacc[4][4];
#pragma unroll
        for (int jf = 0; jf < 4; jf++)
#pragma unroll
            for (int r = 0; r < 4; r++) sacc[jf][r] = 0.f;

#pragma unroll
        for (int kc = 0; kc < 8; kc++) {
            uint4 qh4 = *(const uint4*)&smu[OFF_Q + ((w * 8 + kc) * 32 + lane) * 4];
            uint32_t qha[4] = {qh4.x, qh4.y, qh4.z, qh4.w};
#pragma unroll
            for (int jfp = 0; jfp < 2; jfp++) {
                uint4 kb = *(const uint4*)&Kf[((kc * 2 + jfp) * 32 + lane) * 4];
                mma_fp16(sacc[2 * jfp],     qha, kb.x, kb.y);
                mma_fp16(sacc[2 * jfp + 1], qha, kb.z, kb.w);
            }
        }

        // ---- online softmax (ex2, log2 domain, skip-rescale vote) ----
        float mx0 = fmaxf(fmaxf(sacc[0][0], sacc[0][1]), fmaxf(sacc[1][0], sacc[1][1]));
        mx0 = fmaxf(mx0, fmaxf(fmaxf(sacc[2][0], sacc[2][1]), fmaxf(sacc[3][0], sacc[3][1])));
        float mx1 = fmaxf(fmaxf(sacc[0][2], sacc[0][3]), fmaxf(sacc[1][2], sacc[1][3]));
        mx1 = fmaxf(mx1, fmaxf(fmaxf(sacc[2][2], sacc[2][3]), fmaxf(sacc[3][2], sacc[3][3])));
        mx0 = fmaxf(mx0, __shfl_xor_sync(0xffffffffu, mx0, 1));
        mx0 = fmaxf(mx0, __shfl_xor_sync(0xffffffffu, mx0, 2));
        mx1 = fmaxf(mx1, __shfl_xor_sync(0xffffffffu, mx1, 1));
        mx1 = fmaxf(mx1, __shfl_xor_sync(0xffffffffu, mx1, 2));

        const bool upd = (mx0 > m0) || (mx1 > m1);
        if (__any_sync(0xffffffffu, upd)) {
            float mn0 = fmaxf(m0, mx0), mn1 = fmaxf(m1, mx1);
            float sc0 = ex2f(m0 - mn0), sc1 = ex2f(m1 - mn1);
            m0 = mn0; m1 = mn1;
            l0 *= sc0; l1 *= sc1;
#pragma unroll
            for (int nf = 0; nf < 16; nf++) {
                oacc[nf][0] *= sc0; oacc[nf][1] *= sc0;
                oacc[nf][2] *= sc1; oacc[nf][3] *= sc1;
            }
        }

        float rs0 = 0.f, rs1 = 0.f;
#pragma unroll
        for (int jf = 0; jf < 4; jf++) {
            sacc[jf][0] = ex2f(sacc[jf][0] - m0);
            sacc[jf][1] = ex2f(sacc[jf][1] - m0);
            sacc[jf][2] = ex2f(sacc[jf][2] - m1);
            sacc[jf][3] = ex2f(sacc[jf][3] - m1);
            rs0 += sacc[jf][0] + sacc[jf][1];
            rs1 += sacc[jf][2] + sacc[jf][3];
        }
        l0 += rs0;                 // lane-partial; reduced at end
        l1 += rs1;

        // ---- O += P V : 32 mma ----
#pragma unroll
        for (int kc = 0; kc < 2; kc++) {
            uint32_t pa[4];
            pa[0] = f16x2(sacc[2 * kc][0],     sacc[2 * kc][1]);
            pa[1] = f16x2(sacc[2 * kc][2],     sacc[2 * kc][3]);
            pa[2] = f16x2(sacc[2 * kc + 1][0], sacc[2 * kc + 1][1]);
            pa[3] = f16x2(sacc[2 * kc + 1][2], sacc[2 * kc + 1][3]);
#pragma unroll
            for (int nfp = 0; nfp < 8; nfp++) {
                uint4 vb = *(const uint4*)&Vf[((kc * 8 + nfp) * 32 + lane) * 4];
                mma_fp16(oacc[2 * nfp],     pa, vb.x, vb.y);
                mma_fp16(oacc[2 * nfp + 1], pa, vb.z, vb.w);
            }
        }

        __syncthreads();
        if (kt + 2 < HKT) issue(s, kt + 2);
        cp_commit();
    }

    // ---- reduce l across the 4 tid lanes ----
    l0 += __shfl_xor_sync(0xffffffffu, l0, 1);
    l0 += __shfl_xor_sync(0xffffffffu, l0, 2);
    l1 += __shfl_xor_sync(0xffffffffu, l1, 1);
    l1 += __shfl_xor_sync(0xffffffffu, l1, 2);

    __syncthreads();   // all warps done with pipeline/Q smem before O staging reuse

    // ---- stage O (unnormalized), write partials + m,l ----
    const int r0 = 16 * w + g2;
    float* OSf = (float*)smu;           // [128][132]
#pragma unroll
    for (int nf = 0; nf < 16; nf++) {
        int c = 8 * nf + 2 * tid;
        OSf[c * 132 + r0]           = oacc[nf][0];
        OSf[(c + 1) * 132 + r0]     = oacc[nf][1];
        OSf[c * 132 + r0 + 8]       = oacc[nf][2];
        OSf[(c + 1) * 132 + r0 + 8] = oacc[nf][3];
    }
    if (tid == 0) {
        size_t lb = ((size_t)half * B_ + b) * 4096 + N0;
        g_m[lb + r0]     = m0;
        g_m[lb + r0 + 8] = m1;
        g_l[lb + r0]     = l0;
        g_l[lb + r0 + 8] = l1;
    }
    __syncthreads();

    float* Og = g_Op + ((size_t)half * B_ + b) * (size_t)C_ * N_ + N0;
    for (int v = t; v < 4096; v += 256) {
        int c = v >> 5, q = (v & 31) * 4;
        *(float4*)(Og + (size_t)c * N_ + q) = *(float4*)&OSf[c * 132 + q];
    }
}

// ---------------------------------------------------------------------------
// out-proj fused with split-K combine + gamma + residual, cp.async pipelined.
// ---------------------------------------------------------------------------
#define OP_W   0
#define OP_XS  4224
#define OP_RAW 6272
#define OP_W1  18560
#define OP_W2  18624
#define OP_FLOATS 18688
#define OP_SMEM_BYTES (OP_FLOATS * 4)

__global__ __launch_bounds__(256) void outproj_kernel(
    const float* __restrict__ x, const float* __restrict__ gamma,
    const float* __restrict__ W, const float* __restrict__ bias,
    float* __restrict__ dst)
{
    extern __shared__ float osm[];
    float* Wt  = osm + OP_W;     // [32][132]
    float* xs  = osm + OP_XS;    // [32][64]
    float* w1s = osm + OP_W1;
    float* w2s = osm + OP_W2;

    const int t = threadIdx.x, nblk = blockIdx.x, b = blockIdx.y;
    const int n0 = 8 * (t & 7), o0 = 4 * (t >> 3);
    const int nbase = nblk * 64;

    const uint32_t sbase = (uint32_t)__cvta_generic_to_shared(osm);

    const float* O1 = g_Op + (size_t)b * C_ * N_ + nbase;
    const float* O2 = g_Op + (size_t)(B_ + b) * C_ * N_ + nbase;
    const float* xB = x + (size_t)b * C_ * N_ + nbase;

    auto issue = [&](int s, int kc) {
        const float* srcs[3] = {O1, O2, xB};
#pragma unroll
        for (int p = 0; p < 3; p++) {
#pragma unroll
            for (int r = 0; r < 2; r++) {
                int v = t + 256 * r;
                int k = v >> 4, q = (v & 15) * 4;
                cp_async16(sbase + (OP_RAW + ((s * 3 + p) * 2048) + v * 4) * 4,
                           srcs[p] + (size_t)(kc * 32 + k) * N_ + q);
            }
        }
    };

    issue(0, 0); cp_commit();
    issue(1, 1); cp_commit();

    if (t < 64) {
        size_t i1 = (size_t)b * 4096 + nbase + t;
        size_t i2 = (size_t)(B_ + b) * 4096 + nbase + t;
        float m1 = g_m[i1], m2 = g_m[i2];
        float l1 = g_l[i1], l2 = g_l[i2];
        float m = fmaxf(m1, m2);
        float f1 = ex2f(m1 - m), f2 = ex2f(m2 - m);
        float inv = 1.f / (l1 * f1 + l2 * f2);
        w1s[t] = f1 * inv;
        w2s[t] = f2 * inv;
    }

    const float gm = gamma[0];

    float acc[4][8];
#pragma unroll
    for (int i = 0; i < 4; i++)
#pragma unroll
        for (int j = 0; j < 8; j++) acc[i][j] = 0.f;

#pragma unroll
    for (int kc = 0; kc < 4; kc++) {
        const int s = kc & 1;
        for (int v = t; v < 1024; v += 256) {
            int o = v >> 3, q = v & 7;
            float4 w = *(const float4*)(W + (size_t)o * C_ + kc * 32 + 4 * q);
            Wt[(4 * q + 0) * 132 + o] = w.x;
            Wt[(4 * q + 1) * 132 + o] = w.y;
            Wt[(4 * q + 2) * 132 + o] = w.z;
            Wt[(4 * q + 3) * 132 + o] = w.w;
        }
        cp_wait1();
        __syncthreads();

        {
            const float* r1 = osm + OP_RAW + (s * 3 + 0) * 2048;
            const float* r2 = osm + OP_RAW + (s * 3 + 1) * 2048;
            const float* rx = osm + OP_RAW + (s * 3 + 2) * 2048;
            for (int v = t; v < 512; v += 256) {
                int k = v >> 4, q = (v & 15) * 4;
                float4 o1 = *(const float4*)&r1[k * 64 + q];
                float4 o2 = *(const float4*)&r2[k * 64 + q];
                float4 xv = *(const float4*)&rx[k * 64 + q];
                float4 rr;
                rr.x = gm * (o1.x * w1s[q + 0] + o2.x * w2s[q + 0]) + xv.x;
                rr.y = gm * (o1.y * w1s[q + 1] + o2.y * w2s[q + 1]) + xv.y;
                rr.z = gm * (o1.z * w1s[q + 2] + o2.z * w2s[q + 2]) + xv.z;
                rr.w = gm * (o1.w * w1s[q + 3] + o2.w * w2s[q + 3]) + xv.w;
                *(float4*)&xs[k * 64 + q] = rr;
            }
        }
        __syncthreads();

        if (kc + 2 < 4) issue(s, kc + 2);
        cp_commit();

#pragma unroll
        for (int k = 0; k < 32; k++) {
            float4 w  = *(float4*)&Wt[k * 132 + o0];
            float4 xa = *(float4*)&xs[k * 64 + n0];
            float4 xb = *(float4*)&xs[k * 64 + n0 + 4];
            float wv[4] = {w.x, w.y, w.z, w.w};
            float xv[8] = {xa.x, xa.y, xa.z, xa.w, xb.x, xb.y, xb.z, xb.w};
#pragma unroll
            for (int i = 0; i < 4; i++)
#pragma unroll
                for (int j = 0; j < 8; j++)
                    acc[i][j] = fmaf(wv[i], xv[j], acc[i][j]);
        }
        __syncthreads();
    }

#pragma unroll
    for (int i = 0; i < 4; i++) {
        float bv = bias[o0 + i];
        float* drow = dst + ((size_t)b * 128 + (o0 + i)) * N_ + (size_t)nblk * 64 + n0;
        *(float4*)(drow)     = make_float4(acc[i][0] + bv, acc[i][1] + bv, acc[i][2] + bv, acc[i][3] + bv);
        *(float4*)(drow + 4) = make_float4(acc[i][4] + bv, acc[i][5] + bv, acc[i][6] + bv, acc[i][7] + bv);
    }
}

// ---------------------------------------------------------------------------
extern "C" void kernel_launch(void* const* d_in, const int* in_sizes, int n_in,
                              void* d_out, int out_size)
{
    const float* x     = (const float*)d_in[0];
    const float* Wq    = (const float*)d_in[1];
    const float* bq    = (const float*)d_in[2];
    const float* Wk    = (const float*)d_in[3];
    const float* bk    = (const float*)d_in[4];
    const float* Wv    = (const float*)d_in[5];
    const float* bv    = (const float*)d_in[6];
    const float* gamma = (const float*)d_in[7];
    const float* Wo    = (const float*)d_in[8];
    const float* bo    = (const float*)d_in[9];
    float* out = (float*)d_out;

    cudaFuncSetAttribute(attn_kernel,
                         cudaFuncAttributeMaxDynamicSharedMemorySize, ATTN_SMEM_BYTES);
    cudaFuncSetAttribute(outproj_kernel,
                         cudaFuncAttributeMaxDynamicSharedMemorySize, OP_SMEM_BYTES);

    dim3 p3grid(N_ / 64, B_, 3);
    proj3_kernel<<<p3grid, 256>>>(x, Wq, bq, Wk, bk, Wv, bv);
    pack_qkv_kernel<<<p3grid, 256>>>();

    dim3 agrid(N_ / 128, B_, 2);
    attn_kernel<<<agrid, 256, ATTN_SMEM_BYTES>>>();

    dim3 ogrid(N_ / 64, B_);
    outproj_kernel<<<ogrid, 256, OP_SMEM_BYTES>>>(x, gamma, Wo, bo, out);
}